// round 5
// baseline (speedup 1.0000x reference)
#include <cuda_runtime.h>
#include <cuda_fp16.h>
#include <cstdint>
#include <cfloat>

#define Dd 64
#define Kk 1024
#define TR 128
#define NCH 8

#define BPITCH 144                 // bytes per code row in smem (conflict-free)
#define SMB_BUFSZ (128*BPITCH)     // 18432 per buffer

// ---------------- smem layout (bytes) ----------------
#define SM_B    0                  // 2 buf x 18432 = 36864
#define SM_XS   36864              // 128 x 65 fp32 = 33280  -> 70144
#define SM_CN   70144              // 4096 -> 74240
#define SM_XN   74240              // 512  -> 74752
#define SM_TAU  74752              // 512  -> 75264
#define SM_RV   75264              // 1024 -> 76288
#define SM_RI   76288              // 1024 -> 77312
#define SM_BI   77312              // 512  -> 77824
#define SM_RS   77824              // 1024 -> 78848
#define SM_NREF 78848              // 4
#define SM_RL   78852              // 512  -> 79364
#define SM_TOTAL 79364

// ---------------- scratch ----------------
__device__ float  g_codebookT[Kk*Dd];  // [K][D] exact fp32 (gather + refine)
__device__ float  g_cnorm[Kk];
__device__ __half g_Bh16[Kk*Dd];       // fp16 hi split, permuted rows (128B each)
__device__ int    g_nm_i;              // max_k ||m_k||^2   (float bits, monotonic)
__device__ int    g_nml_i;             // max_k ||m_k - fp16(m_k)||^2
__device__ float  g_blocksum[1024];

// ---------------- helpers ----------------
__device__ __forceinline__ uint32_t smem_u32(const void* p){
    uint32_t a; asm("{ .reg .u64 t; cvta.to.shared.u64 t, %1; cvt.u32.u64 %0, t; }" : "=r"(a) : "l"(p)); return a;
}
__device__ __forceinline__ uint4 lds128(uint32_t a){
    uint4 v; asm volatile("ld.shared.v4.u32 {%0,%1,%2,%3}, [%4];"
        : "=r"(v.x),"=r"(v.y),"=r"(v.z),"=r"(v.w) : "r"(a)); return v;
}
#define CP16(dst, src) asm volatile("cp.async.cg.shared.global [%0], [%1], 16;" :: "r"(dst), "l"(src) : "memory")
#define CP_COMMIT()    asm volatile("cp.async.commit_group;" ::: "memory")
#define CP_WAIT(n)     asm volatile("cp.async.wait_group %0;" :: "n"(n) : "memory")

#define MMA16(c0,c1,c2,c3, a0,a1,a2,a3, b0,b1) \
  asm volatile("mma.sync.aligned.m16n8k16.row.col.f32.f16.f16.f32 " \
    "{%0,%1,%2,%3},{%4,%5,%6,%7},{%8,%9},{%0,%1,%2,%3};" \
    : "+f"(c0),"+f"(c1),"+f"(c2),"+f"(c3) \
    : "r"(a0),"r"(a1),"r"(a2),"r"(a3),"r"(b0),"r"(b1))

#define UPD(bv,bi,bv2, s, idx) do{ float _s=(s); \
    if (_s < (bv)){ (bv2)=(bv); (bv)=_s; (bi)=(idx); } \
    else if (_s < (bv2)) (bv2)=_s; }while(0)

// B-row permutation: dim d -> slot so each lane's 16 values are contiguous.
__device__ __forceinline__ int bslot(int d){
    int s = d >> 4, r = d & 15;
    return ((r >> 1) & 3) * 16 + s * 4 + ((r >> 3) & 1) * 2 + (r & 1);
}

// ---------------------------------------------------------------------------
// Prep: transpose cm[D][K]; exact fp32 copy + fp16 hi split (permuted layout),
// per-code norms + global max norms (for the rigorous screen window).
// ---------------------------------------------------------------------------
__global__ void vq_prep(const float* __restrict__ cm){
    __shared__ float  tile[64][65];
    __shared__ __half hst[64*64];
    const int t  = threadIdx.x;
    const int kb = blockIdx.x * 64;
    const int j  = t & 63;
    const int dr = t >> 6;
#pragma unroll
    for (int i = 0; i < 16; ++i){
        int d = dr + 4*i;
        tile[d][j] = cm[d*Kk + kb + j];
    }
    __syncthreads();
    const int slot = bslot(j);
#pragma unroll
    for (int i = 0; i < 16; ++i){
        int kr = dr + 4*i;
        float v = tile[j][kr];
        g_codebookT[(kb + kr)*Dd + j] = v;
        hst[kr*64 + slot] = __float2half_rn(v);
    }
    if (t < 64){
        float s = 0.f, sl = 0.f;
#pragma unroll
        for (int d = 0; d < 64; ++d){
            float v = tile[d][t];
            float l = v - __half2float(__float2half_rn(v));
            s += v*v; sl += l*l;
        }
        g_cnorm[kb + t] = s;
        atomicMax(&g_nm_i,  __float_as_int(s));
        atomicMax(&g_nml_i, __float_as_int(sl));
    }
    __syncthreads();
    const uint4* hs4 = (const uint4*)hst;
    uint4* gh4 = (uint4*)(g_Bh16 + (size_t)kb * Dd);
#pragma unroll
    for (int i = 0; i < 2; ++i)
        gh4[t + 256*i] = hs4[t + 256*i];
}

// ---------------------------------------------------------------------------
// Main: single fp16 hi*hi screening GEMM + rigorous per-row window; near-tie
// rows re-solved exactly with the R1 fp32 formula. Fused gather/STE/loss.
// ---------------------------------------------------------------------------
__global__ __launch_bounds__(256, 2)
void vq_main(const float* __restrict__ x, float* __restrict__ out,
             float* __restrict__ out_idx)
{
    extern __shared__ char smem[];
    const uint32_t sb = smem_u32(smem);
    float* Xs      = (float*)(smem + SM_XS);
    float* cn_s    = (float*)(smem + SM_CN);
    float* xn_s    = (float*)(smem + SM_XN);
    float* tau_s   = (float*)(smem + SM_TAU);
    float* RV      = (float*)(smem + SM_RV);
    int*   RI      = (int*)  (smem + SM_RI);
    int*   besti_s = (int*)  (smem + SM_BI);
    float* RS      = (float*)(smem + SM_RS);
    int*   nref_p  = (int*)  (smem + SM_NREF);
    int*   reflist = (int*)  (smem + SM_RL);

    const int tid = threadIdx.x;
    const int wid = tid >> 5, lid = tid & 31;
    const int l4  = lid & 3,  gq  = lid >> 2;
    const int row0 = blockIdx.x * TR;

    if (tid == 0) *nref_p = 0;

    // ---- cp.async B chunk 0 (1024 x 16B, hi only) ----
#pragma unroll
    for (int i = 0; i < 4; ++i){
        int e = tid + 256*i;
        int n = e >> 3, grp = e & 7;
        uint64_t src; asm("cvta.to.global.u64 %0, %1;" : "=l"(src)
                          : "l"(g_Bh16 + (size_t)n*Dd + grp*8));
        uint32_t dst = sb + SM_B + (uint32_t)(n*BPITCH + grp*16);
        CP16(dst, src);
    }
    CP_COMMIT();

    // ---- X tile -> Xs (pad 65) + cn_s ----
    {
        const float4* x4 = (const float4*)(x + (size_t)row0 * Dd);
#pragma unroll
        for (int i = 0; i < 8; ++i){
            int e = tid + 256*i;
            int r = e >> 4, g = e & 15;
            float4 v = x4[e];
            Xs[r*65 + g*4 + 0] = v.x; Xs[r*65 + g*4 + 1] = v.y;
            Xs[r*65 + g*4 + 2] = v.z; Xs[r*65 + g*4 + 3] = v.w;
        }
    }
#pragma unroll
    for (int i = 0; i < 4; ++i) cn_s[tid + 256*i] = g_cnorm[tid + 256*i];
    __syncthreads();

    // ---- per-row norms + rigorous screening window ----
    if (tid < 128){
        float s = 0.f, sl = 0.f;
#pragma unroll
        for (int d = 0; d < 64; ++d){
            float v = Xs[tid*65 + d];
            float l = v - __half2float(__float2half_rn(v));
            s += v*v; sl += l*l;
        }
        xn_s[tid] = s;
        float nm  = sqrtf(__int_as_float(g_nm_i));
        float nml = sqrtf(__int_as_float(g_nml_i));
        float xl  = sqrtf(sl), xf = sqrtf(s);
        // |dot_err| <= ||x_lo||*||m|| + ||x_hi||*||m_lo||; score err = 2*dot_err.
        float tdot = xl*nm + (xf + xl)*nml;
        tau_s[tid] = 4.0f*tdot + 1e-3f;   // > 2*(score err) + fp32 slack
    }

    // ---- A fragments: fp16 hi, resident for all chunks ----
    uint32_t Ah[16];
    {
        const int r0 = 16*wid + gq, r1 = r0 + 8;
#pragma unroll
        for (int s = 0; s < 4; ++s){
#pragma unroll
            for (int p = 0; p < 2; ++p){
                int k0 = 16*s + 2*l4 + 8*p;
                __half2 hh;
                hh = __halves2half2(__float2half_rn(Xs[r0*65 + k0]),
                                    __float2half_rn(Xs[r0*65 + k0 + 1]));
                Ah[s*4 + p*2 + 0] = *(uint32_t*)&hh;
                hh = __halves2half2(__float2half_rn(Xs[r1*65 + k0]),
                                    __float2half_rn(Xs[r1*65 + k0 + 1]));
                Ah[s*4 + p*2 + 1] = *(uint32_t*)&hh;
            }
        }
    }

    float bv0 = FLT_MAX, bv20 = FLT_MAX, bv1 = FLT_MAX, bv21 = FLT_MAX;
    int   bi0 = 0, bi1 = 0;

    for (int c = 0; c < NCH; ++c){
        if (c + 1 < NCH){
            const int buf = (c + 1) & 1;
#pragma unroll
            for (int i = 0; i < 4; ++i){
                int e = tid + 256*i;
                int n = e >> 3, grp = e & 7;
                uint64_t src; asm("cvta.to.global.u64 %0, %1;" : "=l"(src)
                                  : "l"(g_Bh16 + (size_t)((c+1)*128 + n)*Dd + grp*8));
                uint32_t dst = sb + SM_B + buf*SMB_BUFSZ + (uint32_t)(n*BPITCH + grp*16);
                CP16(dst, src);
            }
            CP_COMMIT();
            CP_WAIT(1);
        } else {
            CP_WAIT(0);
        }
        __syncthreads();

        const uint32_t bbase = sb + SM_B + (uint32_t)(c & 1) * SMB_BUFSZ
                             + (uint32_t)(gq * BPITCH + l4 * 32);
#pragma unroll
        for (int nt = 0; nt < 16; ++nt){
            const uint32_t nb = bbase + (uint32_t)(nt * 8 * BPITCH);
            uint4 b0 = lds128(nb);
            uint4 b1 = lds128(nb + 16);
            uint32_t bw[8] = {b0.x,b0.y,b0.z,b0.w, b1.x,b1.y,b1.z,b1.w};

            float c0=0.f, c1=0.f, c2=0.f, c3=0.f;
#pragma unroll
            for (int s = 0; s < 4; ++s)
                MMA16(c0,c1,c2,c3, Ah[s*4+0],Ah[s*4+1],Ah[s*4+2],Ah[s*4+3],
                      bw[s*2], bw[s*2+1]);

            const int colb = c*128 + nt*8 + l4*2;
            const float cn0 = cn_s[colb], cn1 = cn_s[colb+1];
            UPD(bv0, bi0, bv20, fmaf(-2.f, c0, cn0), colb);
            UPD(bv0, bi0, bv20, fmaf(-2.f, c1, cn1), colb + 1);
            UPD(bv1, bi1, bv21, fmaf(-2.f, c2, cn0), colb);
            UPD(bv1, bi1, bv21, fmaf(-2.f, c3, cn1), colb + 1);
        }
        __syncthreads();
    }

    // ---- reduce argmin (+ second best) across the 4 lanes per row ----
#pragma unroll
    for (int off = 1; off < 4; off <<= 1){
        float ov  = __shfl_xor_sync(~0u, bv0, off);
        int   oi  = __shfl_xor_sync(~0u, bi0, off);
        float ov2 = __shfl_xor_sync(~0u, bv20, off);
        float lose;
        if (ov < bv0 || (ov == bv0 && oi < bi0)){ lose = bv0; bv0 = ov; bi0 = oi; }
        else lose = ov;
        bv20 = fminf(bv20, fminf(ov2, lose));

        ov  = __shfl_xor_sync(~0u, bv1, off);
        oi  = __shfl_xor_sync(~0u, bi1, off);
        ov2 = __shfl_xor_sync(~0u, bv21, off);
        if (ov < bv1 || (ov == bv1 && oi < bi1)){ lose = bv1; bv1 = ov; bi1 = oi; }
        else lose = ov;
        bv21 = fminf(bv21, fminf(ov2, lose));
    }
    if (l4 == 0){
        const int r0 = 16*wid + gq, r1 = r0 + 8;
        besti_s[r0] = bi0;
        besti_s[r1] = bi1;
        if (bv20 - bv0 < tau_s[r0]){ int s = atomicAdd(nref_p, 1); reflist[s] = r0; }
        if (bv21 - bv1 < tau_s[r1]){ int s = atomicAdd(nref_p, 1); reflist[s] = r1; }
    }
    __syncthreads();

    // ---- exact R1-formula re-solve for flagged rows ----
    const int cnt = *nref_p;
    for (int f = 0; f < cnt; ++f){
        const int row = reflist[f];
        const float xnr = xn_s[row];
        float best = FLT_MAX; int bidx = 0;
#pragma unroll
        for (int kc = 0; kc < 4; ++kc){
            const int k = tid*4 + kc;
            float dot = 0.f;
#pragma unroll
            for (int d = 0; d < 64; ++d)
                dot = fmaf(Xs[row*65 + d], g_codebookT[k*Dd + d], dot);
            float sv = (xnr - 2.0f*dot) + cn_s[k];
            if (sv < best){ best = sv; bidx = k; }
        }
        RV[tid] = best; RI[tid] = bidx;
        __syncthreads();
        for (int s = 128; s > 0; s >>= 1){
            if (tid < s){
                float ov = RV[tid+s]; int oi = RI[tid+s];
                if (ov < RV[tid] || (ov == RV[tid] && oi < RI[tid])){ RV[tid] = ov; RI[tid] = oi; }
            }
            __syncthreads();
        }
        if (tid == 0) besti_s[row] = RI[0];
        __syncthreads();
    }

    // ---- gather + STE output + loss partial ----
    float partial = 0.f;
    if (tid < 128){
        const int bi = besti_s[tid];
        out_idx[row0 + tid] = (float)bi;
        const float4* q4 = (const float4*)(g_codebookT + (size_t)bi * Dd);
        float4* o4 = (float4*)(out + (size_t)(row0 + tid) * Dd);
#pragma unroll
        for (int g = 0; g < 16; ++g){
            float4 q = q4[g];
            float xa = Xs[tid*65 + g*4 + 0];
            float xb = Xs[tid*65 + g*4 + 1];
            float xc = Xs[tid*65 + g*4 + 2];
            float xd = Xs[tid*65 + g*4 + 3];
            float da = q.x - xa, db = q.y - xb, dc = q.z - xc, dd = q.w - xd;
            partial += da*da + db*db + dc*dc + dd*dd;
            float4 o; o.x = xa + da; o.y = xb + db; o.z = xc + dc; o.w = xd + dd;
            o4[g] = o;
        }
    }
    RS[tid] = partial;
    __syncthreads();
    for (int s = 128; s > 0; s >>= 1){
        if (tid < s) RS[tid] += RS[tid + s];
        __syncthreads();
    }
    if (tid == 0) g_blocksum[blockIdx.x] = RS[0];
}

// ---------------------------------------------------------------------------
__global__ void vq_finish(float* __restrict__ out_loss, int nblocks, float inv_total){
    if (threadIdx.x == 0 && blockIdx.x == 0){
        double s = 0.0;
        for (int i = 0; i < nblocks; ++i) s += (double)g_blocksum[i];
        float q_loss = (float)(s * (double)inv_total);
        out_loss[0] = q_loss + 0.25f * q_loss;
    }
}

// ---------------------------------------------------------------------------
extern "C" void kernel_launch(void* const* d_in, const int* in_sizes, int n_in,
                              void* d_out, int out_size) {
    const float* x  = (const float*)d_in[0];
    const float* cm = (const float*)d_in[1];
    float* out = (float*)d_out;

    const int N = in_sizes[0] / Dd;
    float* out_idx  = out + (size_t)N * Dd;
    float* out_loss = out_idx + N;

    cudaFuncSetAttribute(vq_main, cudaFuncAttributeMaxDynamicSharedMemorySize, SM_TOTAL);

    vq_prep<<<Kk/64, 256>>>(cm);
    vq_main<<<N/TR, 256, SM_TOTAL>>>(x, out, out_idx);
    vq_finish<<<1, 32>>>(out_loss, N/TR, 1.0f / (float)(N * Dd));
}

// round 6
// speedup vs baseline: 6.5186x; 6.5186x over previous
#include <cuda_runtime.h>
#include <cuda_fp16.h>
#include <cstdint>
#include <cfloat>

#define Dd 64
#define Kk 1024
#define TR 128
#define NCH 8

#define BPITCH 144                 // bytes per code row in smem (conflict-free)
#define SMB_BUFSZ (128*BPITCH)     // 18432 per buffer

// ---------------- smem layout (bytes) ----------------
#define SM_B    0                  // 2 buf x 18432 = 36864 (also refine stage: 32KB)
#define SM_XS   36864              // 128 x 65 fp32 = 33280  -> 70144
#define SM_CN   70144              // 4096 -> 74240
#define SM_XN   74240              // 512  -> 74752
#define SM_TAU  74752              // 512  -> 75264
#define SM_RV   75264              // 1024 -> 76288
#define SM_RI   76288              // 1024 -> 77312
#define SM_BI   77312              // 512  -> 77824
#define SM_RS   77824              // 1024 -> 78848
#define SM_NREF 78848              // 4
#define SM_RL   78852              // 512  -> 79364
#define SM_TOTAL 79364

// ---------------- scratch ----------------
__device__ float  g_codebookT[Kk*Dd];  // [K][D] exact fp32 (gather)
__device__ float  g_cnorm[Kk];
__device__ __half g_Bh16[Kk*Dd];       // fp16 hi split, permuted rows (128B each)
__device__ int    g_nm_i;              // max_k ||m_k||^2   (float bits, monotonic)
__device__ int    g_nml_i;             // max_k ||m_k - fp16(m_k)||^2
__device__ float  g_blocksum[1024];

// ---------------- helpers ----------------
__device__ __forceinline__ uint32_t smem_u32(const void* p){
    uint32_t a; asm("{ .reg .u64 t; cvta.to.shared.u64 t, %1; cvt.u32.u64 %0, t; }" : "=r"(a) : "l"(p)); return a;
}
__device__ __forceinline__ uint4 lds128(uint32_t a){
    uint4 v; asm volatile("ld.shared.v4.u32 {%0,%1,%2,%3}, [%4];"
        : "=r"(v.x),"=r"(v.y),"=r"(v.z),"=r"(v.w) : "r"(a)); return v;
}
#define CP16(dst, src) asm volatile("cp.async.cg.shared.global [%0], [%1], 16;" :: "r"(dst), "l"(src) : "memory")
#define CP_COMMIT()    asm volatile("cp.async.commit_group;" ::: "memory")
#define CP_WAIT(n)     asm volatile("cp.async.wait_group %0;" :: "n"(n) : "memory")

#define MMA16(c0,c1,c2,c3, a0,a1,a2,a3, b0,b1) \
  asm volatile("mma.sync.aligned.m16n8k16.row.col.f32.f16.f16.f32 " \
    "{%0,%1,%2,%3},{%4,%5,%6,%7},{%8,%9},{%0,%1,%2,%3};" \
    : "+f"(c0),"+f"(c1),"+f"(c2),"+f"(c3) \
    : "r"(a0),"r"(a1),"r"(a2),"r"(a3),"r"(b0),"r"(b1))

#define UPD(bv,bi,bv2, s, idx) do{ float _s=(s); \
    if (_s < (bv)){ (bv2)=(bv); (bv)=_s; (bi)=(idx); } \
    else if (_s < (bv2)) (bv2)=_s; }while(0)

// B-row permutation: dim d -> slot so each lane's 16 values are contiguous.
__device__ __forceinline__ int bslot(int d){
    int s = d >> 4, r = d & 15;
    return ((r >> 1) & 3) * 16 + s * 4 + ((r >> 3) & 1) * 2 + (r & 1);
}

// ---------------------------------------------------------------------------
// Prep: transpose cm[D][K]; exact fp32 copy + fp16 hi split (permuted layout),
// per-code norms + global max norms (for the rigorous screen window).
// ---------------------------------------------------------------------------
__global__ void vq_prep(const float* __restrict__ cm){
    __shared__ float  tile[64][65];
    __shared__ __half hst[64*64];
    const int t  = threadIdx.x;
    const int kb = blockIdx.x * 64;
    const int j  = t & 63;
    const int dr = t >> 6;
#pragma unroll
    for (int i = 0; i < 16; ++i){
        int d = dr + 4*i;
        tile[d][j] = cm[d*Kk + kb + j];
    }
    __syncthreads();
    const int slot = bslot(j);
#pragma unroll
    for (int i = 0; i < 16; ++i){
        int kr = dr + 4*i;
        float v = tile[j][kr];
        g_codebookT[(kb + kr)*Dd + j] = v;
        hst[kr*64 + slot] = __float2half_rn(v);
    }
    if (t < 64){
        float s = 0.f, sl = 0.f;
#pragma unroll
        for (int d = 0; d < 64; ++d){
            float v = tile[d][t];
            float l = v - __half2float(__float2half_rn(v));
            s += v*v; sl += l*l;
        }
        g_cnorm[kb + t] = s;
        atomicMax(&g_nm_i,  __float_as_int(s));
        atomicMax(&g_nml_i, __float_as_int(sl));
    }
    __syncthreads();
    const uint4* hs4 = (const uint4*)hst;
    uint4* gh4 = (uint4*)(g_Bh16 + (size_t)kb * Dd);
#pragma unroll
    for (int i = 0; i < 2; ++i)
        gh4[t + 256*i] = hs4[t + 256*i];
}

// ---------------------------------------------------------------------------
// Main: single fp16 hi*hi screening GEMM + rigorous per-row window; flagged
// rows re-solved exactly by a batched fp32 micro-GEMM (8 rows x 1024 codes,
// codebook staged d-major in smem). Fused gather/STE/loss.
// ---------------------------------------------------------------------------
__global__ __launch_bounds__(256, 2)
void vq_main(const float* __restrict__ x, const float* __restrict__ cm,
             float* __restrict__ out, float* __restrict__ out_idx)
{
    extern __shared__ char smem[];
    const uint32_t sb = smem_u32(smem);
    float* Xs      = (float*)(smem + SM_XS);
    float* cn_s    = (float*)(smem + SM_CN);
    float* xn_s    = (float*)(smem + SM_XN);
    float* tau_s   = (float*)(smem + SM_TAU);
    float* RV      = (float*)(smem + SM_RV);
    int*   RI      = (int*)  (smem + SM_RI);
    int*   besti_s = (int*)  (smem + SM_BI);
    float* RS      = (float*)(smem + SM_RS);
    int*   nref_p  = (int*)  (smem + SM_NREF);
    int*   reflist = (int*)  (smem + SM_RL);
    float* Bst     = (float*)(smem + SM_B);     // refine stage [8][1024]

    const int tid = threadIdx.x;
    const int wid = tid >> 5, lid = tid & 31;
    const int l4  = lid & 3,  gq  = lid >> 2;
    const int row0 = blockIdx.x * TR;

    if (tid == 0) *nref_p = 0;

    // ---- cp.async B chunk 0 (1024 x 16B, hi only) ----
#pragma unroll
    for (int i = 0; i < 4; ++i){
        int e = tid + 256*i;
        int n = e >> 3, grp = e & 7;
        uint64_t src; asm("cvta.to.global.u64 %0, %1;" : "=l"(src)
                          : "l"(g_Bh16 + (size_t)n*Dd + grp*8));
        uint32_t dst = sb + SM_B + (uint32_t)(n*BPITCH + grp*16);
        CP16(dst, src);
    }
    CP_COMMIT();

    // ---- X tile -> Xs (pad 65) + cn_s ----
    {
        const float4* x4 = (const float4*)(x + (size_t)row0 * Dd);
#pragma unroll
        for (int i = 0; i < 8; ++i){
            int e = tid + 256*i;
            int r = e >> 4, g = e & 15;
            float4 v = x4[e];
            Xs[r*65 + g*4 + 0] = v.x; Xs[r*65 + g*4 + 1] = v.y;
            Xs[r*65 + g*4 + 2] = v.z; Xs[r*65 + g*4 + 3] = v.w;
        }
    }
#pragma unroll
    for (int i = 0; i < 4; ++i) cn_s[tid + 256*i] = g_cnorm[tid + 256*i];
    __syncthreads();

    // ---- per-row norms + rigorous screening window ----
    if (tid < 128){
        float s = 0.f, sl = 0.f;
#pragma unroll
        for (int d = 0; d < 64; ++d){
            float v = Xs[tid*65 + d];
            float l = v - __half2float(__float2half_rn(v));
            s += v*v; sl += l*l;
        }
        xn_s[tid] = s;
        float nm  = sqrtf(__int_as_float(g_nm_i));
        float nml = sqrtf(__int_as_float(g_nml_i));
        float xl  = sqrtf(sl), xf = sqrtf(s);
        float tdot = xl*nm + (xf + xl)*nml;
        tau_s[tid] = 4.0f*tdot + 1e-3f;
    }

    // ---- A fragments: fp16 hi, resident for all chunks ----
    uint32_t Ah[16];
    {
        const int r0 = 16*wid + gq, r1 = r0 + 8;
#pragma unroll
        for (int s = 0; s < 4; ++s){
#pragma unroll
            for (int p = 0; p < 2; ++p){
                int k0 = 16*s + 2*l4 + 8*p;
                __half2 hh;
                hh = __halves2half2(__float2half_rn(Xs[r0*65 + k0]),
                                    __float2half_rn(Xs[r0*65 + k0 + 1]));
                Ah[s*4 + p*2 + 0] = *(uint32_t*)&hh;
                hh = __halves2half2(__float2half_rn(Xs[r1*65 + k0]),
                                    __float2half_rn(Xs[r1*65 + k0 + 1]));
                Ah[s*4 + p*2 + 1] = *(uint32_t*)&hh;
            }
        }
    }

    float bv0 = FLT_MAX, bv20 = FLT_MAX, bv1 = FLT_MAX, bv21 = FLT_MAX;
    int   bi0 = 0, bi1 = 0;

    for (int c = 0; c < NCH; ++c){
        if (c + 1 < NCH){
            const int buf = (c + 1) & 1;
#pragma unroll
            for (int i = 0; i < 4; ++i){
                int e = tid + 256*i;
                int n = e >> 3, grp = e & 7;
                uint64_t src; asm("cvta.to.global.u64 %0, %1;" : "=l"(src)
                                  : "l"(g_Bh16 + (size_t)((c+1)*128 + n)*Dd + grp*8));
                uint32_t dst = sb + SM_B + buf*SMB_BUFSZ + (uint32_t)(n*BPITCH + grp*16);
                CP16(dst, src);
            }
            CP_COMMIT();
            CP_WAIT(1);
        } else {
            CP_WAIT(0);
        }
        __syncthreads();

        const uint32_t bbase = sb + SM_B + (uint32_t)(c & 1) * SMB_BUFSZ
                             + (uint32_t)(gq * BPITCH + l4 * 32);
#pragma unroll
        for (int nt = 0; nt < 16; ++nt){
            const uint32_t nb = bbase + (uint32_t)(nt * 8 * BPITCH);
            uint4 b0 = lds128(nb);
            uint4 b1 = lds128(nb + 16);
            uint32_t bw[8] = {b0.x,b0.y,b0.z,b0.w, b1.x,b1.y,b1.z,b1.w};

            float c0=0.f, c1=0.f, c2=0.f, c3=0.f;
#pragma unroll
            for (int s = 0; s < 4; ++s)
                MMA16(c0,c1,c2,c3, Ah[s*4+0],Ah[s*4+1],Ah[s*4+2],Ah[s*4+3],
                      bw[s*2], bw[s*2+1]);

            const int colb = c*128 + nt*8 + l4*2;
            const float cn0 = cn_s[colb], cn1 = cn_s[colb+1];
            UPD(bv0, bi0, bv20, fmaf(-2.f, c0, cn0), colb);
            UPD(bv0, bi0, bv20, fmaf(-2.f, c1, cn1), colb + 1);
            UPD(bv1, bi1, bv21, fmaf(-2.f, c2, cn0), colb);
            UPD(bv1, bi1, bv21, fmaf(-2.f, c3, cn1), colb + 1);
        }
        __syncthreads();
    }

    // ---- reduce argmin (+ second best) across the 4 lanes per row ----
#pragma unroll
    for (int off = 1; off < 4; off <<= 1){
        float ov  = __shfl_xor_sync(~0u, bv0, off);
        int   oi  = __shfl_xor_sync(~0u, bi0, off);
        float ov2 = __shfl_xor_sync(~0u, bv20, off);
        float lose;
        if (ov < bv0 || (ov == bv0 && oi < bi0)){ lose = bv0; bv0 = ov; bi0 = oi; }
        else lose = ov;
        bv20 = fminf(bv20, fminf(ov2, lose));

        ov  = __shfl_xor_sync(~0u, bv1, off);
        oi  = __shfl_xor_sync(~0u, bi1, off);
        ov2 = __shfl_xor_sync(~0u, bv21, off);
        if (ov < bv1 || (ov == bv1 && oi < bi1)){ lose = bv1; bv1 = ov; bi1 = oi; }
        else lose = ov;
        bv21 = fminf(bv21, fminf(ov2, lose));
    }
    if (l4 == 0){
        const int r0 = 16*wid + gq, r1 = r0 + 8;
        besti_s[r0] = bi0;
        besti_s[r1] = bi1;
        if (bv20 - bv0 < tau_s[r0]){ int s = atomicAdd(nref_p, 1); reflist[s] = r0; }
        if (bv21 - bv1 < tau_s[r1]){ int s = atomicAdd(nref_p, 1); reflist[s] = r1; }
    }
    __syncthreads();

    // ---- batched exact refine: groups of 8 rows x all 1024 codes ----
    // Codebook staged d-major ([8 dims][1024 codes]) from cm; thread owns
    // 4 codes x 8 rows of fp32 accumulators. Exact R1 formula & scan order.
    const int cnt = *nref_p;
    for (int g0 = 0; g0 < cnt; g0 += 8){
        const int nr = min(8, cnt - g0);
        int rowid[8];
#pragma unroll
        for (int r = 0; r < 8; ++r)
            rowid[r] = reflist[g0 + ((r < nr) ? r : (nr - 1))];

        float acc[8][4];
#pragma unroll
        for (int r = 0; r < 8; ++r){
            acc[r][0] = 0.f; acc[r][1] = 0.f; acc[r][2] = 0.f; acc[r][3] = 0.f;
        }

        for (int dc = 0; dc < 8; ++dc){
            __syncthreads();   // prior stage consumers done
#pragma unroll
            for (int i = 0; i < 8; ++i){
                int e = tid + 256*i;          // 2048 float4 slots
                int drow = e >> 8;            // 0..7
                int k4 = e & 255;
                float4 v = *(const float4*)(cm + (size_t)(dc*8 + drow)*Kk + k4*4);
                *(float4*)&Bst[drow*1024 + k4*4] = v;
            }
            __syncthreads();
#pragma unroll
            for (int dl = 0; dl < 8; ++dl){
                const int d = dc*8 + dl;
                float4 b = *(const float4*)&Bst[dl*1024 + tid*4];
                float xv[8];
#pragma unroll
                for (int r = 0; r < 8; ++r) xv[r] = Xs[rowid[r]*65 + d];
#pragma unroll
                for (int r = 0; r < 8; ++r){
                    acc[r][0] = fmaf(xv[r], b.x, acc[r][0]);
                    acc[r][1] = fmaf(xv[r], b.y, acc[r][1]);
                    acc[r][2] = fmaf(xv[r], b.z, acc[r][2]);
                    acc[r][3] = fmaf(xv[r], b.w, acc[r][3]);
                }
            }
        }
        __syncthreads();

#pragma unroll
        for (int r = 0; r < 8; ++r){
            const float xnr = xn_s[rowid[r]];
            float best = FLT_MAX; int bidx = 0;
#pragma unroll
            for (int kc = 0; kc < 4; ++kc){
                int k = tid*4 + kc;
                float sv = (xnr - 2.0f*acc[r][kc]) + cn_s[k];
                if (sv < best){ best = sv; bidx = k; }
            }
#pragma unroll
            for (int off = 1; off < 32; off <<= 1){
                float ov = __shfl_xor_sync(~0u, best, off);
                int   oi = __shfl_xor_sync(~0u, bidx, off);
                if (ov < best || (ov == best && oi < bidx)){ best = ov; bidx = oi; }
            }
            if (lid == 0){ RV[r*8 + wid] = best; RI[r*8 + wid] = bidx; }
        }
        __syncthreads();
        if (tid < nr){
            float best = RV[tid*8]; int bidx = RI[tid*8];
#pragma unroll
            for (int w = 1; w < 8; ++w){
                float ov = RV[tid*8 + w]; int oi = RI[tid*8 + w];
                if (ov < best || (ov == best && oi < bidx)){ best = ov; bidx = oi; }
            }
            besti_s[reflist[g0 + tid]] = bidx;
        }
    }
    __syncthreads();

    // ---- gather + STE output + loss partial ----
    float partial = 0.f;
    if (tid < 128){
        const int bi = besti_s[tid];
        out_idx[row0 + tid] = (float)bi;
        const float4* q4 = (const float4*)(g_codebookT + (size_t)bi * Dd);
        float4* o4 = (float4*)(out + (size_t)(row0 + tid) * Dd);
#pragma unroll
        for (int g = 0; g < 16; ++g){
            float4 q = q4[g];
            float xa = Xs[tid*65 + g*4 + 0];
            float xb = Xs[tid*65 + g*4 + 1];
            float xc = Xs[tid*65 + g*4 + 2];
            float xd = Xs[tid*65 + g*4 + 3];
            float da = q.x - xa, db = q.y - xb, dc = q.z - xc, dd = q.w - xd;
            partial += da*da + db*db + dc*dc + dd*dd;
            float4 o; o.x = xa + da; o.y = xb + db; o.z = xc + dc; o.w = xd + dd;
            o4[g] = o;
        }
    }
    RS[tid] = partial;
    __syncthreads();
    for (int s = 128; s > 0; s >>= 1){
        if (tid < s) RS[tid] += RS[tid + s];
        __syncthreads();
    }
    if (tid == 0) g_blocksum[blockIdx.x] = RS[0];
}

// ---------------------------------------------------------------------------
__global__ void vq_finish(float* __restrict__ out_loss, int nblocks, float inv_total){
    if (threadIdx.x == 0 && blockIdx.x == 0){
        double s = 0.0;
        for (int i = 0; i < nblocks; ++i) s += (double)g_blocksum[i];
        float q_loss = (float)(s * (double)inv_total);
        out_loss[0] = q_loss + 0.25f * q_loss;
    }
}

// ---------------------------------------------------------------------------
extern "C" void kernel_launch(void* const* d_in, const int* in_sizes, int n_in,
                              void* d_out, int out_size) {
    const float* x  = (const float*)d_in[0];
    const float* cm = (const float*)d_in[1];
    float* out = (float*)d_out;

    const int N = in_sizes[0] / Dd;
    float* out_idx  = out + (size_t)N * Dd;
    float* out_loss = out_idx + N;

    cudaFuncSetAttribute(vq_main, cudaFuncAttributeMaxDynamicSharedMemorySize, SM_TOTAL);

    vq_prep<<<Kk/64, 256>>>(cm);
    vq_main<<<N/TR, 256, SM_TOTAL>>>(x, cm, out, out_idx);
    vq_finish<<<1, 32>>>(out_loss, N/TR, 1.0f / (float)(N * Dd));
}

// round 7
// speedup vs baseline: 11.1119x; 1.7046x over previous
#include <cuda_runtime.h>
#include <cuda_fp16.h>
#include <cstdint>
#include <cfloat>

#define Dd 64
#define Kk 1024
#define TR 64                      // rows per CTA -> 1024 tiles (kills per-SM quantization)
#define NCH 8

#define BPITCH 144                 // bytes per code row in smem (conflict-free)
#define SMB_BUFSZ (128*BPITCH)     // 18432 per buffer

// ---------------- smem layout (bytes) ----------------
#define SM_B    0                  // 2 x 18432 = 36864
#define SM_XS   36864              // 64 x 65 fp32 = 16640 -> 53504
#define SM_CN   53504              // 4096 -> 57600
#define SM_XN   57600              // 256  -> 57856
#define SM_TAU  57856              // 256  -> 58112
#define SM_HM   58112              // halfmin [2][64][8] f32 = 4096 -> 62208
#define SM_RVH  62208              // 128 f32 -> 62720
#define SM_RIH  62720              // 128 int -> 63232
#define SM_RV2H 63232              // 128 f32 -> 63744
#define SM_BI   63744              // 64 int -> 64000
#define SM_RES  64000              // 64 x u64 -> 64512 (8B aligned)
#define SM_ITM  64512              // 512 int -> 66560
#define SM_FLG  66560              // 64 int -> 66816
#define SM_CNT  66816              // 8
#define SM_RS   66824              // 256 f32 -> 67848
#define SM_TOTAL 67848

// ---------------- scratch ----------------
__device__ float  g_codebookT[Kk*Dd];  // [K][D] exact fp32 (gather)
__device__ float  g_cnorm[Kk];
__device__ __half g_Bh16[Kk*Dd];       // fp16 hi, permuted rows (128B each)
__device__ int    g_nm_i;              // max ||m||^2 (float bits, monotonic)
__device__ int    g_nml_i;             // max ||m - fp16(m)||^2
__device__ float  g_blocksum[1024];

// ---------------- helpers ----------------
__device__ __forceinline__ uint32_t smem_u32(const void* p){
    uint32_t a; asm("{ .reg .u64 t; cvta.to.shared.u64 t, %1; cvt.u32.u64 %0, t; }" : "=r"(a) : "l"(p)); return a;
}
__device__ __forceinline__ uint4 lds128(uint32_t a){
    uint4 v; asm volatile("ld.shared.v4.u32 {%0,%1,%2,%3}, [%4];"
        : "=r"(v.x),"=r"(v.y),"=r"(v.z),"=r"(v.w) : "r"(a)); return v;
}
#define CP16(dst, src) asm volatile("cp.async.cg.shared.global [%0], [%1], 16;" :: "r"(dst), "l"(src) : "memory")
#define CP_COMMIT()    asm volatile("cp.async.commit_group;" ::: "memory")
#define CP_WAIT(n)     asm volatile("cp.async.wait_group %0;" :: "n"(n) : "memory")

#define MMA16(c0,c1,c2,c3, a0,a1,a2,a3, b0,b1) \
  asm volatile("mma.sync.aligned.m16n8k16.row.col.f32.f16.f16.f32 " \
    "{%0,%1,%2,%3},{%4,%5,%6,%7},{%8,%9},{%0,%1,%2,%3};" \
    : "+f"(c0),"+f"(c1),"+f"(c2),"+f"(c3) \
    : "r"(a0),"r"(a1),"r"(a2),"r"(a3),"r"(b0),"r"(b1))

#define UPD(bv,bi,bv2, s, idx) do{ float _s=(s); \
    if (_s < (bv)){ (bv2)=(bv); (bv)=_s; (bi)=(idx); } \
    else if (_s < (bv2)) (bv2)=_s; }while(0)

__device__ __forceinline__ int bslot(int d){
    int s = d >> 4, r = d & 15;
    return ((r >> 1) & 3) * 16 + s * 4 + ((r >> 3) & 1) * 2 + (r & 1);
}

__device__ __forceinline__ unsigned long long packsi(float s, int idx){
    uint32_t u = __float_as_uint(s);
    u = (u >> 31) ? ~u : (u | 0x80000000u);   // order-preserving float->uint
    return ((unsigned long long)u << 10) | (uint32_t)idx;
}

// ---------------------------------------------------------------------------
// Prep: 64 blocks x 16 codes — transpose, fp16 hi split (permuted), norms.
// ---------------------------------------------------------------------------
__global__ void vq_prep(const float* __restrict__ cm){
    __shared__ float tile[64][17];
    const int t  = threadIdx.x;
    const int kb = blockIdx.x * 16;
#pragma unroll
    for (int i = 0; i < 4; ++i){
        int e = t + 256*i;            // 0..1023
        int d = e >> 4, j = e & 15;
        tile[d][j] = cm[d*Kk + kb + j];
    }
    __syncthreads();
#pragma unroll
    for (int i = 0; i < 4; ++i){
        int e = t + 256*i;
        int kr = e >> 6, j = e & 63;  // kr 0..15, j dim
        float v = tile[j][kr];
        g_codebookT[(kb + kr)*Dd + j] = v;
        g_Bh16[(kb + kr)*Dd + bslot(j)] = __float2half_rn(v);
    }
    if (t < 16){
        float s = 0.f, sl = 0.f;
#pragma unroll
        for (int d = 0; d < 64; ++d){
            float v = tile[d][t];
            float l = v - __half2float(__float2half_rn(v));
            s += v*v; sl += l*l;
        }
        g_cnorm[kb + t] = s;
        atomicMax(&g_nm_i,  __float_as_int(s));
        atomicMax(&g_nml_i, __float_as_int(sl));
    }
}

// ---------------------------------------------------------------------------
// Main: fp16 hi*hi screen (warp = 16 rows x 64-code half), per-chunk minima,
// rigorous tau flag, chunk-granular exact refine, gather/STE/loss.
// ---------------------------------------------------------------------------
__global__ __launch_bounds__(256, 2)
void vq_main(const float* __restrict__ x, const float* __restrict__ cm,
             float* __restrict__ out, float* __restrict__ out_idx)
{
    extern __shared__ char smem[];
    const uint32_t sb = smem_u32(smem);
    float* Xs    = (float*)(smem + SM_XS);
    float* cn_s  = (float*)(smem + SM_CN);
    float* xn_s  = (float*)(smem + SM_XN);
    float* tau_s = (float*)(smem + SM_TAU);
    float* hm_s  = (float*)(smem + SM_HM);
    float* RVh   = (float*)(smem + SM_RVH);
    int*   RIh   = (int*)  (smem + SM_RIH);
    float* RV2h  = (float*)(smem + SM_RV2H);
    int*   besti_s = (int*)(smem + SM_BI);
    unsigned long long* res_s = (unsigned long long*)(smem + SM_RES);
    int*   items = (int*)  (smem + SM_ITM);
    int*   flg_s = (int*)  (smem + SM_FLG);
    int*   nit_p = (int*)  (smem + SM_CNT);
    float* RS    = (float*)(smem + SM_RS);

    const int tid = threadIdx.x;
    const int wid = tid >> 5, lid = tid & 31;
    const int l4  = lid & 3,  gq  = lid >> 2;
    const int colhalf = wid >> 2;          // 0/1: which 64-code half
    const int rq = wid & 3;                // row quad
    const int r0 = rq*16 + gq, r1 = r0 + 8;
    const int row0 = blockIdx.x * TR;

    if (tid == 0) *nit_p = 0;

    // ---- cp.async B chunk 0 ----
#pragma unroll
    for (int i = 0; i < 4; ++i){
        int e = tid + 256*i;
        int n = e >> 3, grp = e & 7;
        uint64_t src; asm("cvta.to.global.u64 %0, %1;" : "=l"(src)
                          : "l"(g_Bh16 + (size_t)n*Dd + grp*8));
        uint32_t dst = sb + SM_B + (uint32_t)(n*BPITCH + grp*16);
        CP16(dst, src);
    }
    CP_COMMIT();

    // ---- X tile [64 x 64] -> Xs (pad 65) + cn_s ----
    {
        const float4* x4 = (const float4*)(x + (size_t)row0 * Dd);
#pragma unroll
        for (int i = 0; i < 4; ++i){
            int e = tid + 256*i;          // 0..1023 float4s
            int r = e >> 4, g = e & 15;
            float4 v = x4[e];
            Xs[r*65 + g*4 + 0] = v.x; Xs[r*65 + g*4 + 1] = v.y;
            Xs[r*65 + g*4 + 2] = v.z; Xs[r*65 + g*4 + 3] = v.w;
        }
    }
#pragma unroll
    for (int i = 0; i < 4; ++i) cn_s[tid + 256*i] = g_cnorm[tid + 256*i];
    __syncthreads();

    // ---- per-row norms + rigorous screening window ----
    if (tid < 64){
        float s = 0.f, sl = 0.f;
#pragma unroll
        for (int d = 0; d < 64; ++d){
            float v = Xs[tid*65 + d];
            float l = v - __half2float(__float2half_rn(v));
            s += v*v; sl += l*l;
        }
        xn_s[tid] = s;
        float nm  = sqrtf(__int_as_float(g_nm_i));
        float nml = sqrtf(__int_as_float(g_nml_i));
        float xl  = sqrtf(sl), xf = sqrtf(s);
        float tdot = xl*nm + (xf + xl)*nml;
        tau_s[tid] = 4.0f*tdot + 1e-3f;
    }

    // ---- A fragments: fp16 hi ----
    uint32_t Ah[16];
#pragma unroll
    for (int s = 0; s < 4; ++s){
#pragma unroll
        for (int p = 0; p < 2; ++p){
            int k0 = 16*s + 2*l4 + 8*p;
            __half2 hh;
            hh = __halves2half2(__float2half_rn(Xs[r0*65 + k0]),
                                __float2half_rn(Xs[r0*65 + k0 + 1]));
            Ah[s*4 + p*2 + 0] = *(uint32_t*)&hh;
            hh = __halves2half2(__float2half_rn(Xs[r1*65 + k0]),
                                __float2half_rn(Xs[r1*65 + k0 + 1]));
            Ah[s*4 + p*2 + 1] = *(uint32_t*)&hh;
        }
    }

    float bv0 = FLT_MAX, bv20 = FLT_MAX, bv1 = FLT_MAX, bv21 = FLT_MAX;
    int   bi0 = 0, bi1 = 0;

    // ---- chunk loop: one sync per chunk ----
    for (int c = 0; c < NCH; ++c){
        CP_WAIT(0);
        __syncthreads();
        if (c + 1 < NCH){
            const int buf = (c + 1) & 1;
#pragma unroll
            for (int i = 0; i < 4; ++i){
                int e = tid + 256*i;
                int n = e >> 3, grp = e & 7;
                uint64_t src; asm("cvta.to.global.u64 %0, %1;" : "=l"(src)
                                  : "l"(g_Bh16 + (size_t)((c+1)*128 + n)*Dd + grp*8));
                uint32_t dst = sb + SM_B + buf*SMB_BUFSZ + (uint32_t)(n*BPITCH + grp*16);
                CP16(dst, src);
            }
            CP_COMMIT();
        }

        const uint32_t bbase = sb + SM_B + (uint32_t)(c & 1) * SMB_BUFSZ
                             + (uint32_t)((colhalf*64 + gq) * BPITCH + l4 * 32);
        float cmin0 = FLT_MAX, cmin1 = FLT_MAX;
#pragma unroll
        for (int nt = 0; nt < 8; ++nt){
            const uint32_t nb = bbase + (uint32_t)(nt * 8 * BPITCH);
            uint4 b0 = lds128(nb);
            uint4 b1 = lds128(nb + 16);
            uint32_t bw[8] = {b0.x,b0.y,b0.z,b0.w, b1.x,b1.y,b1.z,b1.w};

            float c0=0.f, c1=0.f, c2=0.f, c3=0.f;
#pragma unroll
            for (int s = 0; s < 4; ++s)
                MMA16(c0,c1,c2,c3, Ah[s*4+0],Ah[s*4+1],Ah[s*4+2],Ah[s*4+3],
                      bw[s*2], bw[s*2+1]);

            const int colb = c*128 + colhalf*64 + nt*8 + l4*2;
            const float2 cn2 = *(const float2*)&cn_s[colb];
            float s0 = fmaf(-2.f, c0, cn2.x);
            float s1 = fmaf(-2.f, c1, cn2.y);
            float s2 = fmaf(-2.f, c2, cn2.x);
            float s3 = fmaf(-2.f, c3, cn2.y);
            UPD(bv0, bi0, bv20, s0, colb);
            UPD(bv0, bi0, bv20, s1, colb + 1);
            UPD(bv1, bi1, bv21, s2, colb);
            UPD(bv1, bi1, bv21, s3, colb + 1);
            cmin0 = fminf(cmin0, fminf(s0, s1));
            cmin1 = fminf(cmin1, fminf(s2, s3));
        }
        // quad-reduce chunk minima, store halfmin
        cmin0 = fminf(cmin0, __shfl_xor_sync(~0u, cmin0, 1));
        cmin0 = fminf(cmin0, __shfl_xor_sync(~0u, cmin0, 2));
        cmin1 = fminf(cmin1, __shfl_xor_sync(~0u, cmin1, 1));
        cmin1 = fminf(cmin1, __shfl_xor_sync(~0u, cmin1, 2));
        if (l4 == 0){
            hm_s[(colhalf*64 + r0)*8 + c] = cmin0;
            hm_s[(colhalf*64 + r1)*8 + c] = cmin1;
        }
    }

    // ---- quad-reduce global best/second ----
#pragma unroll
    for (int off = 1; off < 4; off <<= 1){
        float ov  = __shfl_xor_sync(~0u, bv0, off);
        int   oi  = __shfl_xor_sync(~0u, bi0, off);
        float ov2 = __shfl_xor_sync(~0u, bv20, off);
        float lose;
        if (ov < bv0 || (ov == bv0 && oi < bi0)){ lose = bv0; bv0 = ov; bi0 = oi; }
        else lose = ov;
        bv20 = fminf(bv20, fminf(ov2, lose));

        ov  = __shfl_xor_sync(~0u, bv1, off);
        oi  = __shfl_xor_sync(~0u, bi1, off);
        ov2 = __shfl_xor_sync(~0u, bv21, off);
        if (ov < bv1 || (ov == bv1 && oi < bi1)){ lose = bv1; bv1 = ov; bi1 = oi; }
        else lose = ov;
        bv21 = fminf(bv21, fminf(ov2, lose));
    }
    if (l4 == 0){
        RVh [colhalf*64 + r0] = bv0;  RIh[colhalf*64 + r0] = bi0;  RV2h[colhalf*64 + r0] = bv20;
        RVh [colhalf*64 + r1] = bv1;  RIh[colhalf*64 + r1] = bi1;  RV2h[colhalf*64 + r1] = bv21;
    }
    __syncthreads();

    // ---- merge halves, flag, build (row,chunk) items ----
    if (tid < 64){
        float v0 = RVh[tid],    v1 = RVh[64+tid];
        int   i0 = RIh[tid],    i1 = RIh[64+tid];
        float s0 = RV2h[tid],   s1 = RV2h[64+tid];
        float bv; int bi; float sec;
        if (v1 < v0 || (v1 == v0 && i1 < i0)){ bv = v1; bi = i1; sec = fminf(v0, s1); }
        else                                  { bv = v0; bi = i0; sec = fminf(v1, s0); }
        besti_s[tid] = bi;
        const float tau = tau_s[tid];
        int fl = (sec - bv < tau) ? 1 : 0;
        flg_s[tid] = fl;
        if (fl){
            res_s[tid] = ~0ull;
            const float lim = bv + tau;
#pragma unroll
            for (int c = 0; c < 8; ++c){
                float cmn = fminf(hm_s[tid*8 + c], hm_s[(64+tid)*8 + c]);
                if (cmn <= lim){
                    int s = atomicAdd(nit_p, 1);
                    items[s] = (tid << 3) | c;
                }
            }
        }
    }
    __syncthreads();

    // ---- chunk-granular exact refine: warp per item ----
    const int nitems = *nit_p;
    for (int it = wid; it < nitems; it += 8){
        const int item = items[it];
        const int row = item >> 3, ch = item & 7;
        float a0 = 0.f, a1 = 0.f, a2 = 0.f, a3 = 0.f;
        const float4* bp = (const float4*)(cm + ch*128) + lid;   // +256 float4 per dim
#pragma unroll 16
        for (int d = 0; d < 64; ++d){
            float4 b = __ldg(bp + d*256);
            float xv = Xs[row*65 + d];
            a0 = fmaf(xv, b.x, a0);
            a1 = fmaf(xv, b.y, a1);
            a2 = fmaf(xv, b.z, a2);
            a3 = fmaf(xv, b.w, a3);
        }
        const float xnr = xn_s[row];
        const int k0 = ch*128 + lid*4;
        float best = (xnr - 2.0f*a0) + cn_s[k0];     int bidx = k0;
        float sv;
        sv = (xnr - 2.0f*a1) + cn_s[k0+1]; if (sv < best){ best = sv; bidx = k0+1; }
        sv = (xnr - 2.0f*a2) + cn_s[k0+2]; if (sv < best){ best = sv; bidx = k0+2; }
        sv = (xnr - 2.0f*a3) + cn_s[k0+3]; if (sv < best){ best = sv; bidx = k0+3; }
#pragma unroll
        for (int off = 16; off > 0; off >>= 1){
            float ov = __shfl_xor_sync(~0u, best, off);
            int   oi = __shfl_xor_sync(~0u, bidx, off);
            if (ov < best || (ov == best && oi < bidx)){ best = ov; bidx = oi; }
        }
        if (lid == 0) atomicMin(&res_s[row], packsi(best, bidx));
    }
    __syncthreads();
    if (tid < 64 && flg_s[tid])
        besti_s[tid] = (int)(res_s[tid] & 0x3FFull);
    __syncthreads();

    // ---- gather + STE output + loss (thread = quarter row) ----
    float partial = 0.f;
    {
        const int row = tid >> 2, q = tid & 3;
        const int bi = besti_s[row];
        if (q == 0) out_idx[row0 + row] = (float)bi;
        const float4* q4 = (const float4*)(g_codebookT + (size_t)bi * Dd) + q*4;
        float4* o4 = (float4*)(out + (size_t)(row0 + row) * Dd) + q*4;
#pragma unroll
        for (int g = 0; g < 4; ++g){
            float4 qv = q4[g];
            int db = q*16 + g*4;
            float xa = Xs[row*65 + db + 0];
            float xb = Xs[row*65 + db + 1];
            float xc = Xs[row*65 + db + 2];
            float xd = Xs[row*65 + db + 3];
            float da = qv.x - xa, dbv = qv.y - xb, dc = qv.z - xc, dd = qv.w - xd;
            partial += da*da + dbv*dbv + dc*dc + dd*dd;
            float4 o; o.x = xa + da; o.y = xb + dbv; o.z = xc + dc; o.w = xd + dd;
            o4[g] = o;
        }
    }
    RS[tid] = partial;
    __syncthreads();
    for (int s = 128; s > 0; s >>= 1){
        if (tid < s) RS[tid] += RS[tid + s];
        __syncthreads();
    }
    if (tid == 0) g_blocksum[blockIdx.x] = RS[0];
}

// ---------------------------------------------------------------------------
// Final loss: deterministic two-level fp64 sum (fixed order).
// ---------------------------------------------------------------------------
__global__ void vq_finish(float* __restrict__ out_loss, int nblocks, float inv_total){
    __shared__ double part[32];
    const int t = threadIdx.x;
    if (blockIdx.x == 0 && t < 32){
        double s = 0.0;
        const int per = nblocks / 32;
        for (int i = 0; i < per; ++i) s += (double)g_blocksum[t*per + i];
        part[t] = s;
        __syncwarp();
        if (t == 0){
            double tot = 0.0;
            for (int i = 0; i < 32; ++i) tot += part[i];
            float q_loss = (float)(tot * (double)inv_total);
            out_loss[0] = q_loss + 0.25f * q_loss;
        }
    }
}

// ---------------------------------------------------------------------------
extern "C" void kernel_launch(void* const* d_in, const int* in_sizes, int n_in,
                              void* d_out, int out_size) {
    const float* x  = (const float*)d_in[0];
    const float* cm = (const float*)d_in[1];
    float* out = (float*)d_out;

    const int N = in_sizes[0] / Dd;            // 65536
    float* out_idx  = out + (size_t)N * Dd;
    float* out_loss = out_idx + N;

    cudaFuncSetAttribute(vq_main, cudaFuncAttributeMaxDynamicSharedMemorySize, SM_TOTAL);

    vq_prep<<<Kk/16, 256>>>(cm);
    vq_main<<<N/TR, 256, SM_TOTAL>>>(x, cm, out, out_idx);
    vq_finish<<<1, 32>>>(out_loss, N/TR, 1.0f / (float)(N * Dd));
}